// round 17
// baseline (speedup 1.0000x reference)
#include <cuda_runtime.h>
#include <cuda_bf16.h>

// BitGatConv — algebraic collapse (verified R1-R13, rel_err ~3e-7):
//   vals[i,c] = nhs[i,c] * sum_j softmax(...)[i,j,c] = nhs[i,c]
// => out = nodes_ft @ weight  : [1536,256] @ [256,64]
//
// R16: R15 structure (barrier-independent iteration 0) with the staging
// mask bug fixed: NF_Q=768 is NOT a power of two, so `tid & (NF_Q-1)`
// corrupted rows 256..511. Now a plain predicated load.
//  - k4=0 node values + weights prefetched via LDG, computed BEFORE the
//    stage barrier (overlaps node-tile DRAM latency)
//  - k4=1..3 from warm smem tile + L1 weights
//  - f32x2 FMA, RPT=3, KSPLIT=16, 128 blocks x 1024 thr
//  - aliased 48 KB publish + 192-thread parallel f32x2 reduce

#define NROWS        1536
#define KDIM         256
#define K4           (KDIM / 4)          // 64 float4 per row
#define HCDIM        64
#define ROWS_PER_BLK 12
#define RPT          3                    // rows per thread (g, g+4, g+8)
#define NG           (ROWS_PER_BLK / RPT) // 4 row-groups
#define GRID         (NROWS / ROWS_PER_BLK)   // 128 blocks = 1/SM
#define KSPLIT       16
#define GROUP        (NG * 16)                // 64 threads per K-slice
#define THREADS      (GROUP * KSPLIT)         // 1024
#define K4_PER_TH    (K4 / KSPLIT)            // 4
#define NF_Q         (ROWS_PER_BLK * K4)      // 768 float4 = 12 KB
#define BUF_Q        (KSPLIT * RPT * GROUP)   // 3072 float4 = 48 KB exactly

// packed f32x2 helpers
#define SPLAT2(d, f) asm("mov.b64 %0, {%1, %1};" : "=l"(d) : "r"(__float_as_uint(f)))
#define FMA2(d, a, b, c) asm("fma.rn.f32x2 %0, %1, %2, %3;" : "=l"(d) : "l"(a), "l"(b), "l"(c))
#define ADD2(d, a, b) asm("add.rn.f32x2 %0, %1, %2;" : "=l"(d) : "l"(a), "l"(b))

union F2U { unsigned long long u; float2 f; };

__global__ __launch_bounds__(THREADS, 1)
void bitgat_nhs_kernel(const float* __restrict__ nodes_ft,
                       const float* __restrict__ weight,
                       float* __restrict__ out)
{
    // [0..12KB) doubles as node tile during compute; whole 48 KB = partials after
    __shared__ float4 s_buf[BUF_Q];

    const int tid  = threadIdx.x;
    const int row0 = blockIdx.x * ROWS_PER_BLK;

    const int kh  = tid >> 6;             // 0..15 K-slice
    const int rem = tid & 63;
    const int g   = rem >> 4;             // 0..3 row group -> rows g, g+4, g+8
    const int cq  = rem & 15;             // 0..15 col quad

    const float4* __restrict__ nf4 = reinterpret_cast<const float4*>(nodes_ft);
    const float4* __restrict__ src = nf4 + (size_t)row0 * K4;
    const ulonglong2* __restrict__ w =
        reinterpret_cast<const ulonglong2*>(weight) + (size_t)(kh * K4_PER_TH * 4) * 16 + cq;

    // ---- k4=0 prefetches (independent of the stage barrier) ----
    const ulonglong2 pw0 = w[0 * 16];                    // k4=0 weights
    const ulonglong2 pw1 = w[1 * 16];
    const ulonglong2 pw2 = w[2 * 16];
    const ulonglong2 pw3 = w[3 * 16];

    const int kb = kh * K4_PER_TH;                       // k4=0 node values, lane-dedup'd
    const float4 pa0 = nf4[(size_t)(row0 + g)     * K4 + kb];
    const float4 pa1 = nf4[(size_t)(row0 + g + 4) * K4 + kb];
    const float4 pa2 = nf4[(size_t)(row0 + g + 8) * K4 + kb];

    // ---- stage node tile (predicated; FIXED: no bogus mask) ----
    if (tid < NF_Q)
        s_buf[tid] = src[tid];

    // 3 rows x 4 cols accumulators as packed f32x2 pairs
    unsigned long long acc[RPT * 2] = {0ull, 0ull, 0ull, 0ull, 0ull, 0ull};

    unsigned long long s;
    #define PROC(F0, F1, F2, W) \
        SPLAT2(s, F0); FMA2(acc[0], s, W.x, acc[0]); FMA2(acc[1], s, W.y, acc[1]); \
        SPLAT2(s, F1); FMA2(acc[2], s, W.x, acc[2]); FMA2(acc[3], s, W.y, acc[3]); \
        SPLAT2(s, F2); FMA2(acc[4], s, W.x, acc[4]); FMA2(acc[5], s, W.y, acc[5]);

    // ---- k4 = 0: pure register compute, runs BEFORE the barrier ----
    PROC(pa0.x, pa1.x, pa2.x, pw0)
    PROC(pa0.y, pa1.y, pa2.y, pw1)
    PROC(pa0.z, pa1.z, pa2.z, pw2)
    PROC(pa0.w, pa1.w, pa2.w, pw3)

    __syncthreads();

    const float4* __restrict__ a0 = &s_buf[(g + 0) * K4 + kb];
    const float4* __restrict__ a1 = &s_buf[(g + 4) * K4 + kb];
    const float4* __restrict__ a2 = &s_buf[(g + 8) * K4 + kb];

    // ---- k4 = 1..3: smem nodes + L1 weights ----
    #pragma unroll
    for (int k4 = 1; k4 < K4_PER_TH; ++k4) {
        const float4 av0 = a0[k4];                       // LDS.128 broadcast
        const float4 av1 = a1[k4];
        const float4 av2 = a2[k4];
        const ulonglong2 w0 = w[(4 * k4 + 0) * 16];      // LDG.128, 256B/warp
        const ulonglong2 w1 = w[(4 * k4 + 1) * 16];
        const ulonglong2 w2 = w[(4 * k4 + 2) * 16];
        const ulonglong2 w3 = w[(4 * k4 + 3) * 16];

        PROC(av0.x, av1.x, av2.x, w0)
        PROC(av0.y, av1.y, av2.y, w1)
        PROC(av0.z, av1.z, av2.z, w2)
        PROC(av0.w, av1.w, av2.w, w3)
    }
    #undef PROC

    // ---- drain node-tile reads, then ALL slices publish (SoA, conflict-free) ----
    __syncthreads();
    #pragma unroll
    for (int c = 0; c < RPT; ++c) {
        ulonglong2 v; v.x = acc[2 * c]; v.y = acc[2 * c + 1];
        *reinterpret_cast<ulonglong2*>(&s_buf[(kh * RPT + c) * GROUP + rem]) = v;
    }
    __syncthreads();

    // ---- parallel reduce: 192 threads, one output float4 each ----
    if (tid < RPT * GROUP) {
        const int c   = tid >> 6;        // 0..2
        const int rr  = tid & 63;
        const int gg  = rr >> 4;         // 0..3
        const int qq  = rr & 15;         // 0..15

        unsigned long long s0 = 0ull, s1 = 0ull;
        #pragma unroll
        for (int sl = 0; sl < KSPLIT; ++sl) {
            const ulonglong2 p =
                *reinterpret_cast<const ulonglong2*>(&s_buf[(sl * RPT + c) * GROUP + rr]);
            ADD2(s0, s0, p.x);
            ADD2(s1, s1, p.y);
        }
        F2U lo, hi; lo.u = s0; hi.u = s1;
        float4* dst = reinterpret_cast<float4*>(out + (size_t)(row0 + gg + 4 * c) * HCDIM);
        dst[qq] = make_float4(lo.f.x, lo.f.y, hi.f.x, hi.f.y);   // STG.128
    }
}

extern "C" void kernel_launch(void* const* d_in, const int* in_sizes, int n_in,
                              void* d_out, int out_size)
{
    // metadata order: nodes_ft, adj_bias_mat, weight, conv_weight1, conv_weight2
    const float* nodes_ft = (const float*)d_in[0];
    const float* weight   = (const float*)d_in[2];
    float* out = (float*)d_out;

    (void)in_sizes; (void)n_in; (void)out_size;

    bitgat_nhs_kernel<<<GRID, THREADS>>>(nodes_ft, weight, out);
}